// round 12
// baseline (speedup 1.0000x reference)
#include <cuda_runtime.h>
#include <cstdint>

#define BB   128
#define SS   64
#define DD   32
#define ND   200000
#define NNZT 4000000
#define NW   6250   // ND/32
#define WPR  6256   // padded words/row
#define BN   128    // columns per block in k_mma
#define ST   36     // shared tile stride (floats) -> conflict-free frags

// ---------------- device scratch ----------------
__device__ float    g_s_set[BB * DD];
__device__ float    g_common[BB * DD];
__device__ float    g_colsum[ND];
__device__ float    g_dinv[ND];
__device__ float    g_diffacc[BB * DD];
__device__ float    g_cdacc[BB * DD];
__device__ float    g_sdiff[BB];
__device__ unsigned g_bits[BB * WPR];
__device__ double   g_bce;
__device__ double   g_neg1;

// ---------------- helpers ----------------
__device__ __forceinline__ float fast_tanh(float x) {
    float r;
    asm("tanh.approx.f32 %0, %1;" : "=f"(r) : "f"(x));
    return r;
}
__device__ __forceinline__ unsigned tf32r(float v) {
    unsigned u;
    asm("cvt.rna.tf32.f32 %0, %1;" : "=r"(u) : "f"(v));
    return u;
}
__device__ __forceinline__ void mma8(float* c,
                                     unsigned a0, unsigned a1, unsigned a2, unsigned a3,
                                     unsigned b0, unsigned b1) {
    asm volatile(
        "mma.sync.aligned.m16n8k8.row.col.f32.tf32.tf32.f32 "
        "{%0,%1,%2,%3}, {%4,%5,%6,%7}, {%8,%9}, {%0,%1,%2,%3};"
        : "+f"(c[0]), "+f"(c[1]), "+f"(c[2]), "+f"(c[3])
        : "r"(a0), "r"(a1), "r"(a2), "r"(a3), "r"(b0), "r"(b1));
}

// fp32 recompute of t = s_set[b] . dhat[n] for near-threshold fixup (rare)
__device__ __noinline__ float fixdot(const float* __restrict__ drug_emb, int b, int n) {
    float inv = g_dinv[n];
    const float4* dp = (const float4*)(drug_emb + (size_t)(n + 1) * DD);
    const float4* sp = (const float4*)(g_s_set + b * DD);
    float acc = 0.f;
#pragma unroll
    for (int q = 0; q < 8; q++) {
        float4 dv = dp[q], sv = sp[q];
        acc += (dv.x * sv.x + dv.y * sv.y) + (dv.z * sv.z + dv.w * sv.w);
    }
    return acc * inv;
}

// ---------------- kernel 0: zero accumulators ----------------
__global__ void k_init() {
    int i = blockIdx.x * blockDim.x + threadIdx.x;
    if (i < BB * DD) { g_diffacc[i] = 0.f; g_cdacc[i] = 0.f; }
    if (i < BB) g_sdiff[i] = 0.f;
    if (i == 0) { g_bce = 0.0; g_neg1 = 0.0; }
}

// ---------------- kernel 1: pack binary drugs to bits ----------------
__global__ void k_pack(const float* __restrict__ drugs) {
    int lane = threadIdx.x & 31;
    int gw = blockIdx.x * (blockDim.x >> 5) + (threadIdx.x >> 5);
    int wstride = gridDim.x * (blockDim.x >> 5);
    int total = BB * NW;
    for (; gw < total; gw += wstride) {
        int row = gw / NW, word = gw - row * NW;
        float v = drugs[(size_t)row * ND + word * 32 + lane];
        unsigned m = __ballot_sync(0xffffffffu, v != 0.f);
        if (lane == 0) g_bits[row * WPR + word] = m;
    }
}

// ---------------- kernel 1b: per-drug inverse norms ----------------
__global__ void k_norm(const float* __restrict__ drug_emb) {
    int n = blockIdx.x * blockDim.x + threadIdx.x;
    if (n < ND) {
        const float4* rp = (const float4*)(drug_emb + (size_t)(n + 1) * DD);
        float ss = 0.f;
#pragma unroll
        for (int q = 0; q < DD / 4; q++) {
            float4 v = rp[q];
            ss += v.x * v.x + v.y * v.y + v.z * v.z + v.w * v.w;
        }
        g_dinv[n] = 1.0f / fmaxf(sqrtf(ss), 1e-12f);
    }
}

// ---------------- kernel 2: s_set + common_embed ----------------
__global__ void k_attn(const int* __restrict__ syms, const int* __restrict__ simidx,
                       const float* __restrict__ sym_emb,
                       const float* __restrict__ w, const float* __restrict__ bvec) {
    int b = blockIdx.x;
    int s = threadIdx.x;
    __shared__ float sw[DD];
    __shared__ float sl[SS];
    __shared__ float sred[SS][DD];
    __shared__ float smax, ssum;
    if (s < DD) sw[s] = w[s];
    float b0 = bvec[0];
    __syncthreads();

    int sym = syms[b * SS + s];
    float x[DD];
    {
        const float4* rp = (const float4*)(sym_emb + (size_t)sym * DD);
#pragma unroll
        for (int q = 0; q < DD / 4; q++) {
            float4 v = rp[q];
            x[4 * q + 0] = v.x; x[4 * q + 1] = v.y; x[4 * q + 2] = v.z; x[4 * q + 3] = v.w;
        }
    }
    float lg = 0.f;
#pragma unroll
    for (int k = 0; k < DD; k++) lg += x[k] * sw[k];
    lg += b0;
    sl[s] = lg;
    __syncthreads();
    if (s == 0) { float m = sl[0]; for (int j = 1; j < SS; j++) m = fmaxf(m, sl[j]); smax = m; }
    __syncthreads();
    float e = expf(lg - smax);
    sl[s] = e;
    __syncthreads();
    if (s == 0) { float t = 0.f; for (int j = 0; j < SS; j++) t += sl[j]; ssum = t; }
    __syncthreads();
    float alpha = e / ssum;
#pragma unroll
    for (int k = 0; k < DD; k++) sred[s][k] = alpha * x[k];
    __syncthreads();
    if (s < DD) {
        float acc = 0.f;
        for (int j = 0; j < SS; j++) acc += sred[j][s];
        float sq = acc * acc;
#pragma unroll
        for (int off = 16; off; off >>= 1) sq += __shfl_xor_sync(0xffffffffu, sq, off);
        float nrm = fmaxf(sqrtf(sq), 1e-12f);
        g_s_set[b * DD + s] = acc / nrm;
    }
    __syncthreads();

    int sb = simidx[b];
    int sym2 = syms[sb * SS + s];
    float vals = (float)(sym * sym2);
    float y[DD];
    {
        const float4* rp = (const float4*)(sym_emb + (size_t)s * DD);
#pragma unroll
        for (int q = 0; q < DD / 4; q++) {
            float4 v = rp[q];
            y[4 * q + 0] = vals * v.x; y[4 * q + 1] = vals * v.y;
            y[4 * q + 2] = vals * v.z; y[4 * q + 3] = vals * v.w;
        }
    }
    lg = 0.f;
#pragma unroll
    for (int k = 0; k < DD; k++) lg += y[k] * sw[k];
    lg += b0;
    sl[s] = lg;
    __syncthreads();
    if (s == 0) { float m = sl[0]; for (int j = 1; j < SS; j++) m = fmaxf(m, sl[j]); smax = m; }
    __syncthreads();
    e = expf(lg - smax);
    sl[s] = e;
    __syncthreads();
    if (s == 0) { float t = 0.f; for (int j = 0; j < SS; j++) t += sl[j]; ssum = t; }
    __syncthreads();
    alpha = e / ssum;
#pragma unroll
    for (int k = 0; k < DD; k++) sred[s][k] = alpha * y[k];
    __syncthreads();
    if (s < DD) {
        float acc = 0.f;
        for (int j = 0; j < SS; j++) acc += sred[j][s];
        g_common[b * DD + s] = acc;
    }
}

// ---------------- kernel 3: sparse diff/cd accumulation over bit rows ------
__global__ void __launch_bounds__(256) k_diffcd(
    const int* __restrict__ simidx, const float* __restrict__ drug_emb) {
    int b = blockIdx.x >> 2;
    int quarter = blockIdx.x & 3;
    int warp = threadIdx.x >> 5, lane = threadIdx.x & 31;
    int sb = simidx[b];
    const unsigned* ow_row = g_bits + (size_t)b * WPR;
    const unsigned* sw_row = g_bits + (size_t)sb * WPR;

    float accd = 0.f, accc = 0.f;
    int cnt = 0;
    int w0 = quarter * 1563;
    int w1 = min(w0 + 1563, NW);
    for (int w = w0 + warp; w < w1; w += 8) {
        unsigned ow = ow_row[w], sw = sw_row[w];
        unsigned x = ow ^ sw;
        unsigned a = ow & sw;
        cnt += __popc(x);
        while (x) {
            int j = __ffs(x) - 1; x &= (x - 1);
            int n = w * 32 + j;
            accd += drug_emb[(size_t)(n + 1) * DD + lane] * g_dinv[n];
        }
        while (a) {
            int j = __ffs(a) - 1; a &= (a - 1);
            int n = w * 32 + j;
            accc += drug_emb[(size_t)(n + 1) * DD + lane] * g_dinv[n];
        }
    }
    __shared__ float sd[8][DD], sc[8][DD];
    __shared__ int scnt[8];
    sd[warp][lane] = accd;
    sc[warp][lane] = accc;
    if (lane == 0) scnt[warp] = cnt;
    __syncthreads();
    if (warp == 0) {
        float t1 = 0.f, t2 = 0.f;
        int c = 0;
        for (int wq = 0; wq < 8; wq++) { t1 += sd[wq][lane]; t2 += sc[wq][lane]; c += scnt[wq]; }
        atomicAdd(&g_diffacc[b * DD + lane], t1);
        atomicAdd(&g_cdacc[b * DD + lane], t2);
        if (lane == 0) atomicAdd(&g_sdiff[b], (float)c);
    }
}

// ---------------- kernel 4: tensor-core mainloop + fp32 fixup --------------
// grid = ceil(ND/BN), 256 threads (8 warps). Warp w owns 16 columns.
__global__ void __launch_bounds__(256) k_mma(
    const float* __restrict__ drug_emb, float* __restrict__ out) {
    extern __shared__ unsigned dynsmem[];
    unsigned* s_sh = dynsmem;                 // [BB][ST] tf32 s_set
    unsigned* c_sh = s_sh + BB * ST;          // [BB][ST] tf32 common
    unsigned* d_sh = c_sh + BB * ST;          // [BN][ST] tf32 d-hat
    float* s_cs  = (float*)(d_sh + BN * ST);  // [BN] colsum
    float* s_red = s_cs + BN;                 // [256]

    int tid = threadIdx.x;
    int w = tid >> 5, lane = tid & 31;
    int g = lane >> 2, tig = lane & 3;
    int n0b = blockIdx.x * BN;

    // stage s_set / common (tf32-rounded)
    for (int i = tid; i < BB * DD; i += 256) {
        int b = i >> 5, k = i & 31;
        s_sh[b * ST + k] = tf32r(g_s_set[i]);
        c_sh[b * ST + k] = tf32r(g_common[i]);
    }
    // stage normalized d rows (tf32-rounded); pad cols -> zero
    for (int i = tid; i < BN * 8; i += 256) {
        int r = i >> 3, q = i & 7;
        int n = n0b + r;
        uint4 u = {0u, 0u, 0u, 0u};
        if (n < ND) {
            float inv = g_dinv[n];
            float4 v = ((const float4*)(drug_emb + (size_t)(n + 1) * DD))[q];
            u.x = tf32r(v.x * inv); u.y = tf32r(v.y * inv);
            u.z = tf32r(v.z * inv); u.w = tf32r(v.w * inv);
        }
        *(uint4*)&d_sh[r * ST + q * 4] = u;
    }
    if (tid < BN) s_cs[tid] = 0.f;
    __syncthreads();

    float zs = 0.f, as_ = 0.f;
    float cs[4] = {0.f, 0.f, 0.f, 0.f};
    int colbase = w * 16;

    for (int mt = 0; mt < 8; mt++) {
        int b0 = mt * 16;
        float ta[2][4] = {{0.f,0.f,0.f,0.f},{0.f,0.f,0.f,0.f}};
        float za[2][4] = {{0.f,0.f,0.f,0.f},{0.f,0.f,0.f,0.f}};

#pragma unroll
        for (int ks = 0; ks < 4; ks++) {
            int k0 = ks * 8;
            const unsigned* sr = s_sh + (b0 + g) * ST + k0 + tig;
            unsigned sa0 = sr[0],          sa2 = sr[4];
            unsigned sa1 = sr[8 * ST],     sa3 = sr[8 * ST + 4];
            const unsigned* cr = c_sh + (b0 + g) * ST + k0 + tig;
            unsigned ca0 = cr[0],          ca2 = cr[4];
            unsigned ca1 = cr[8 * ST],     ca3 = cr[8 * ST + 4];
#pragma unroll
            for (int nt = 0; nt < 2; nt++) {
                const unsigned* dr = d_sh + (colbase + nt * 8 + g) * ST + k0 + tig;
                unsigned bb0 = dr[0], bb1 = dr[4];
                mma8(ta[nt], sa0, sa1, sa2, sa3, bb0, bb1);
                mma8(za[nt], ca0, ca1, ca2, ca3, bb0, bb1);
            }
        }

        // epilogue
#pragma unroll
        for (int nt = 0; nt < 2; nt++) {
            int ncl = n0b + colbase + nt * 8 + 2 * tig;   // col of c0 (even)
            bool v = (ncl < ND);                          // pair never straddles ND
            int r0 = b0 + g, r1 = r0 + 8;

            float t0 = ta[nt][0], t1 = ta[nt][1], t2 = ta[nt][2], t3 = ta[nt][3];
            // fp32 fixup near threshold (tf32 |t| error hard-bounded < ~1.1e-3)
            if (v) {
                if (fabsf(t0) < 4e-3f) t0 = fixdot(drug_emb, r0, ncl);
                if (fabsf(t1) < 4e-3f) t1 = fixdot(drug_emb, r0, ncl + 1);
                if (fabsf(t2) < 4e-3f) t2 = fixdot(drug_emb, r1, ncl);
                if (fabsf(t3) < 4e-3f) t3 = fixdot(drug_emb, r1, ncl + 1);
            }
            float s0 = (t0 > 0.f) ? __fmaf_rn(0.5f, fast_tanh(0.5f * t0), 0.5f) : 0.f;
            float s1 = (t1 > 0.f) ? __fmaf_rn(0.5f, fast_tanh(0.5f * t1), 0.5f) : 0.f;
            float s2 = (t2 > 0.f) ? __fmaf_rn(0.5f, fast_tanh(0.5f * t2), 0.5f) : 0.f;
            float s3 = (t3 > 0.f) ? __fmaf_rn(0.5f, fast_tanh(0.5f * t3), 0.5f) : 0.f;
            if (v) {
                *(float2*)(out + (size_t)r0 * ND + ncl) = make_float2(s0, s1);
                *(float2*)(out + (size_t)r1 * ND + ncl) = make_float2(s2, s3);
            }
            cs[2 * nt]     += s0 + s2;
            cs[2 * nt + 1] += s1 + s3;

            float z0 = za[nt][0], z1 = za[nt][1], z2 = za[nt][2], z3 = za[nt][3];
            zs  += (z0 + z1) + (z2 + z3);
            as_ += (fabsf(z0) + fabsf(z1)) + (fabsf(z2) + fabsf(z3));
        }
    }

    // colsum: 8 threads per column -> shared atomics (small)
    atomicAdd(&s_cs[colbase + 2 * tig],     cs[0]);
    atomicAdd(&s_cs[colbase + 2 * tig + 1], cs[1]);
    atomicAdd(&s_cs[colbase + 8 + 2 * tig],     cs[2]);
    atomicAdd(&s_cs[colbase + 8 + 2 * tig + 1], cs[3]);

    // Sigma max(z,0) = 0.5*(Sigma z + Sigma |z|)  (softplus tail negligible at |z|~1e5)
    s_red[tid] = 0.5f * zs + 0.5f * as_;
    __syncthreads();
    for (int st = 128; st; st >>= 1) {
        if (tid < st) s_red[tid] += s_red[tid + st];
        __syncthreads();
    }
    if (tid == 0) atomicAdd(&g_bce, (double)s_red[0]);

    if (tid < BN) {
        int n = n0b + tid;
        if (n < ND) g_colsum[n] = s_cs[tid];
    }
}

// ---------------- kernel 5: batch_neg gather ----------------
__global__ void k_tail2(const int* __restrict__ idx, const float* __restrict__ val) {
    __shared__ float sred[256];
    int tid = threadIdx.x;
    int i = blockIdx.x * blockDim.x + tid;
    int stride = gridDim.x * blockDim.x;
    float acc = 0.f;
    for (int j = i; j < NNZT; j += stride) acc += val[j] * g_colsum[idx[j]];
    sred[tid] = acc;
    __syncthreads();
    for (int st = 128; st; st >>= 1) {
        if (tid < st) sred[tid] += sred[tid + st];
        __syncthreads();
    }
    if (tid == 0) atomicAdd(&g_neg1, (double)sred[0]);
}

// ---------------- kernel 6: scalars ----------------
__global__ void k_final(float* __restrict__ out) {
    int b = threadIdx.x;   // 128
    __shared__ float sred[BB];
    __shared__ double scd[BB];
    float acc = 0.f;
    double cdot = 0.0;
    float sdv = g_sdiff[b] + 1e-6f;
#pragma unroll
    for (int k = 0; k < DD; k++) {
        float cm = g_common[b * DD + k];
        cdot += (double)cm * (double)g_cdacc[b * DD + k];
        float de = g_diffacc[b * DD + k] / sdv;
        float x = cm * de;
        acc += 1.0f / (1.0f + __expf(-x));
    }
    sred[b] = acc;
    scd[b] = cdot;
    __syncthreads();
    for (int st = 64; st; st >>= 1) {
        if (b < st) { sred[b] += sred[b + st]; scd[b] += scd[b + st]; }
        __syncthreads();
    }
    if (b == 0) {
        double total = g_bce - scd[0];
        out[(size_t)BB * ND]     = (float)(total / ((double)BB * (double)ND));
        out[(size_t)BB * ND + 1] = (float)(1e-6 * g_neg1 + 1e-4 * (double)sred[0]);
    }
}

// ---------------- launcher ----------------
extern "C" void kernel_launch(void* const* d_in, const int* in_sizes, int n_in,
                              void* d_out, int out_size) {
    const int*   syms     = (const int*)d_in[0];
    const float* drugs    = (const float*)d_in[1];
    const int*   simidx   = (const int*)d_in[2];
    const int*   ddi_idx  = (const int*)d_in[3];
    const float* ddi_val  = (const float*)d_in[4];
    const float* sym_emb  = (const float*)d_in[5];
    const float* drug_emb = (const float*)d_in[6];
    const float* attn_w   = (const float*)d_in[7];
    const float* attn_b   = (const float*)d_in[8];
    float* out = (float*)d_out;

    static bool attr_set = false;
    const int smem_mma = (2 * BB * ST + BN * ST) * 4 + BN * 4 + 256 * 4;
    if (!attr_set) {
        cudaFuncSetAttribute(k_mma, cudaFuncAttributeMaxDynamicSharedMemorySize, smem_mma);
        attr_set = true;
    }

    k_init<<<32, 256>>>();
    k_attn<<<BB, SS>>>(syms, simidx, sym_emb, attn_w, attn_b);
    k_norm<<<(ND + 255) / 256, 256>>>(drug_emb);
    k_mma<<<(ND + BN - 1) / BN, 256, smem_mma>>>(drug_emb, out);
    k_pack<<<1024, 256>>>(drugs);
    k_diffcd<<<BB * 4, 256>>>(simidx, drug_emb);
    k_tail2<<<1024, 256>>>(ddi_idx, ddi_val);
    k_final<<<1, BB>>>(out);
}

// round 13
// speedup vs baseline: 1.2568x; 1.2568x over previous
#include <cuda_runtime.h>
#include <cstdint>

#define BB   128
#define SS   64
#define DD   32
#define ND   200000
#define NNZT 4000000
#define NW   6250   // ND/32
#define WPR  6256   // padded words/row
#define BN   128    // columns per block in k_mma
#define ST   36     // shared tile stride (floats) -> conflict-free frags
#define DCB  16     // diffcd blocks per b
#define DCW  391    // words per diffcd block (16*391 >= NW)

// ---------------- device scratch ----------------
__device__ float    g_s_set[BB * DD];
__device__ float    g_common[BB * DD];
__device__ float    g_colsum[ND];
__device__ float    g_dinv[ND];
__device__ float    g_diffacc[BB * DD];
__device__ float    g_cdacc[BB * DD];
__device__ float    g_sdiff[BB];
__device__ unsigned g_bits[BB * WPR];
__device__ double   g_bce;
__device__ double   g_neg1;

// ---------------- helpers ----------------
__device__ __forceinline__ float fast_tanh(float x) {
    float r;
    asm("tanh.approx.f32 %0, %1;" : "=f"(r) : "f"(x));
    return r;
}
__device__ __forceinline__ unsigned tf32r(float v) {
    unsigned u;
    asm("cvt.rna.tf32.f32 %0, %1;" : "=r"(u) : "f"(v));
    return u;
}
__device__ __forceinline__ void mma8(float* c,
                                     unsigned a0, unsigned a1, unsigned a2, unsigned a3,
                                     unsigned b0, unsigned b1) {
    asm volatile(
        "mma.sync.aligned.m16n8k8.row.col.f32.tf32.tf32.f32 "
        "{%0,%1,%2,%3}, {%4,%5,%6,%7}, {%8,%9}, {%0,%1,%2,%3};"
        : "+f"(c[0]), "+f"(c[1]), "+f"(c[2]), "+f"(c[3])
        : "r"(a0), "r"(a1), "r"(a2), "r"(a3), "r"(b0), "r"(b1));
}

// fp32 recompute of t = s_set[b] . dhat[n] (rare near-threshold fixup)
__device__ __noinline__ float fixdot(const float* __restrict__ drug_emb, int b, int n) {
    float inv = g_dinv[n];
    const float4* dp = (const float4*)(drug_emb + (size_t)(n + 1) * DD);
    const float4* sp = (const float4*)(g_s_set + b * DD);
    float acc = 0.f;
#pragma unroll
    for (int q = 0; q < 8; q++) {
        float4 dv = dp[q], sv = sp[q];
        acc += (dv.x * sv.x + dv.y * sv.y) + (dv.z * sv.z + dv.w * sv.w);
    }
    return acc * inv;
}

// ---------------- kernel 0: zero accumulators ----------------
__global__ void k_init() {
    int i = blockIdx.x * blockDim.x + threadIdx.x;
    if (i < BB * DD) { g_diffacc[i] = 0.f; g_cdacc[i] = 0.f; }
    if (i < BB) g_sdiff[i] = 0.f;
    if (i == 0) { g_bce = 0.0; g_neg1 = 0.0; }
}

// ---------------- kernel 1: pack binary drugs to bits ----------------
__global__ void k_pack(const float* __restrict__ drugs) {
    int lane = threadIdx.x & 31;
    int gw = blockIdx.x * (blockDim.x >> 5) + (threadIdx.x >> 5);
    int wstride = gridDim.x * (blockDim.x >> 5);
    int total = BB * NW;
    for (; gw < total; gw += wstride) {
        int row = gw / NW, word = gw - row * NW;
        float v = drugs[(size_t)row * ND + word * 32 + lane];
        unsigned m = __ballot_sync(0xffffffffu, v != 0.f);
        if (lane == 0) g_bits[row * WPR + word] = m;
    }
}

// ---------------- kernel 1b: per-drug inverse norms ----------------
__global__ void k_norm(const float* __restrict__ drug_emb) {
    int n = blockIdx.x * blockDim.x + threadIdx.x;
    if (n < ND) {
        const float4* rp = (const float4*)(drug_emb + (size_t)(n + 1) * DD);
        float ss = 0.f;
#pragma unroll
        for (int q = 0; q < DD / 4; q++) {
            float4 v = rp[q];
            ss += v.x * v.x + v.y * v.y + v.z * v.z + v.w * v.w;
        }
        g_dinv[n] = 1.0f / fmaxf(sqrtf(ss), 1e-12f);
    }
}

// ---------------- kernel 2: s_set + common_embed ----------------
__global__ void k_attn(const int* __restrict__ syms, const int* __restrict__ simidx,
                       const float* __restrict__ sym_emb,
                       const float* __restrict__ w, const float* __restrict__ bvec) {
    int b = blockIdx.x;
    int s = threadIdx.x;
    __shared__ float sw[DD];
    __shared__ float sl[SS];
    __shared__ float sred[SS][DD];
    __shared__ float smax, ssum;
    if (s < DD) sw[s] = w[s];
    float b0 = bvec[0];
    __syncthreads();

    int sym = syms[b * SS + s];
    float x[DD];
    {
        const float4* rp = (const float4*)(sym_emb + (size_t)sym * DD);
#pragma unroll
        for (int q = 0; q < DD / 4; q++) {
            float4 v = rp[q];
            x[4 * q + 0] = v.x; x[4 * q + 1] = v.y; x[4 * q + 2] = v.z; x[4 * q + 3] = v.w;
        }
    }
    float lg = 0.f;
#pragma unroll
    for (int k = 0; k < DD; k++) lg += x[k] * sw[k];
    lg += b0;
    sl[s] = lg;
    __syncthreads();
    if (s == 0) { float m = sl[0]; for (int j = 1; j < SS; j++) m = fmaxf(m, sl[j]); smax = m; }
    __syncthreads();
    float e = expf(lg - smax);
    sl[s] = e;
    __syncthreads();
    if (s == 0) { float t = 0.f; for (int j = 0; j < SS; j++) t += sl[j]; ssum = t; }
    __syncthreads();
    float alpha = e / ssum;
#pragma unroll
    for (int k = 0; k < DD; k++) sred[s][k] = alpha * x[k];
    __syncthreads();
    if (s < DD) {
        float acc = 0.f;
        for (int j = 0; j < SS; j++) acc += sred[j][s];
        float sq = acc * acc;
#pragma unroll
        for (int off = 16; off; off >>= 1) sq += __shfl_xor_sync(0xffffffffu, sq, off);
        float nrm = fmaxf(sqrtf(sq), 1e-12f);
        g_s_set[b * DD + s] = acc / nrm;
    }
    __syncthreads();

    int sb = simidx[b];
    int sym2 = syms[sb * SS + s];
    float vals = (float)(sym * sym2);
    float y[DD];
    {
        const float4* rp = (const float4*)(sym_emb + (size_t)s * DD);
#pragma unroll
        for (int q = 0; q < DD / 4; q++) {
            float4 v = rp[q];
            y[4 * q + 0] = vals * v.x; y[4 * q + 1] = vals * v.y;
            y[4 * q + 2] = vals * v.z; y[4 * q + 3] = vals * v.w;
        }
    }
    lg = 0.f;
#pragma unroll
    for (int k = 0; k < DD; k++) lg += y[k] * sw[k];
    lg += b0;
    sl[s] = lg;
    __syncthreads();
    if (s == 0) { float m = sl[0]; for (int j = 1; j < SS; j++) m = fmaxf(m, sl[j]); smax = m; }
    __syncthreads();
    e = expf(lg - smax);
    sl[s] = e;
    __syncthreads();
    if (s == 0) { float t = 0.f; for (int j = 0; j < SS; j++) t += sl[j]; ssum = t; }
    __syncthreads();
    alpha = e / ssum;
#pragma unroll
    for (int k = 0; k < DD; k++) sred[s][k] = alpha * y[k];
    __syncthreads();
    if (s < DD) {
        float acc = 0.f;
        for (int j = 0; j < SS; j++) acc += sred[j][s];
        g_common[b * DD + s] = acc;
    }
}

// ---------------- kernel 3: sparse diff/cd accumulation over bit rows ------
// grid = BB*DCB, 256 threads (8 warps). lane = embed dim.
__global__ void __launch_bounds__(256) k_diffcd(
    const int* __restrict__ simidx, const float* __restrict__ drug_emb) {
    int b = blockIdx.x / DCB;
    int part = blockIdx.x - b * DCB;
    int warp = threadIdx.x >> 5, lane = threadIdx.x & 31;
    int sb = simidx[b];
    const unsigned* ow_row = g_bits + (size_t)b * WPR;
    const unsigned* sw_row = g_bits + (size_t)sb * WPR;

    float accd = 0.f, accc = 0.f;
    int cnt = 0;
    int w0 = part * DCW;
    int w1 = min(w0 + DCW, NW);
    for (int w = w0 + warp; w < w1; w += 8) {
        unsigned ow = ow_row[w], sw = sw_row[w];
        unsigned x = ow ^ sw;
        unsigned a = ow & sw;
        cnt += __popc(x);
        while (x) {
            int j = __ffs(x) - 1; x &= (x - 1);
            int n = w * 32 + j;
            accd += drug_emb[(size_t)(n + 1) * DD + lane] * g_dinv[n];
        }
        while (a) {
            int j = __ffs(a) - 1; a &= (a - 1);
            int n = w * 32 + j;
            accc += drug_emb[(size_t)(n + 1) * DD + lane] * g_dinv[n];
        }
    }
    __shared__ float sd[8][DD], sc[8][DD];
    __shared__ int scnt[8];
    sd[warp][lane] = accd;
    sc[warp][lane] = accc;
    if (lane == 0) scnt[warp] = cnt;
    __syncthreads();
    if (warp == 0) {
        float t1 = 0.f, t2 = 0.f;
        int c = 0;
        for (int wq = 0; wq < 8; wq++) { t1 += sd[wq][lane]; t2 += sc[wq][lane]; c += scnt[wq]; }
        atomicAdd(&g_diffacc[b * DD + lane], t1);
        atomicAdd(&g_cdacc[b * DD + lane], t2);
        if (lane == 0) atomicAdd(&g_sdiff[b], (float)c);
    }
}

// ---------------- kernel 4: tensor-core mainloop + fp32 fixup --------------
__global__ void __launch_bounds__(256) k_mma(
    const float* __restrict__ drug_emb, float* __restrict__ out) {
    extern __shared__ unsigned dynsmem[];
    unsigned* s_sh = dynsmem;                 // [BB][ST] tf32 s_set
    unsigned* c_sh = s_sh + BB * ST;          // [BB][ST] tf32 common
    unsigned* d_sh = c_sh + BB * ST;          // [BN][ST] tf32 d-hat
    float* s_cs  = (float*)(d_sh + BN * ST);  // [BN] colsum
    float* s_red = s_cs + BN;                 // [256]

    int tid = threadIdx.x;
    int w = tid >> 5, lane = tid & 31;
    int g = lane >> 2, tig = lane & 3;
    int n0b = blockIdx.x * BN;

    for (int i = tid; i < BB * DD; i += 256) {
        int b = i >> 5, k = i & 31;
        s_sh[b * ST + k] = tf32r(g_s_set[i]);
        c_sh[b * ST + k] = tf32r(g_common[i]);
    }
    for (int i = tid; i < BN * 8; i += 256) {
        int r = i >> 3, q = i & 7;
        int n = n0b + r;
        uint4 u = {0u, 0u, 0u, 0u};
        if (n < ND) {
            float inv = g_dinv[n];
            float4 v = ((const float4*)(drug_emb + (size_t)(n + 1) * DD))[q];
            u.x = tf32r(v.x * inv); u.y = tf32r(v.y * inv);
            u.z = tf32r(v.z * inv); u.w = tf32r(v.w * inv);
        }
        *(uint4*)&d_sh[r * ST + q * 4] = u;
    }
    if (tid < BN) s_cs[tid] = 0.f;
    __syncthreads();

    float zs = 0.f, as_ = 0.f;
    float cs[4] = {0.f, 0.f, 0.f, 0.f};
    int colbase = w * 16;

    // hoist B-fragments (mt-invariant): [ks][nt][2]
    unsigned bf[4][2][2];
#pragma unroll
    for (int ks = 0; ks < 4; ks++)
#pragma unroll
        for (int nt = 0; nt < 2; nt++) {
            const unsigned* dr = d_sh + (colbase + nt * 8 + g) * ST + ks * 8 + tig;
            bf[ks][nt][0] = dr[0];
            bf[ks][nt][1] = dr[4];
        }

    for (int mt = 0; mt < 8; mt++) {
        int b0 = mt * 16;
        float ta[2][4] = {{0.f,0.f,0.f,0.f},{0.f,0.f,0.f,0.f}};
        float za[2][4] = {{0.f,0.f,0.f,0.f},{0.f,0.f,0.f,0.f}};

#pragma unroll
        for (int ks = 0; ks < 4; ks++) {
            int k0 = ks * 8;
            const unsigned* sr = s_sh + (b0 + g) * ST + k0 + tig;
            unsigned sa0 = sr[0],          sa2 = sr[4];
            unsigned sa1 = sr[8 * ST],     sa3 = sr[8 * ST + 4];
            const unsigned* cr = c_sh + (b0 + g) * ST + k0 + tig;
            unsigned ca0 = cr[0],          ca2 = cr[4];
            unsigned ca1 = cr[8 * ST],     ca3 = cr[8 * ST + 4];
#pragma unroll
            for (int nt = 0; nt < 2; nt++) {
                mma8(ta[nt], sa0, sa1, sa2, sa3, bf[ks][nt][0], bf[ks][nt][1]);
                mma8(za[nt], ca0, ca1, ca2, ca3, bf[ks][nt][0], bf[ks][nt][1]);
            }
        }

#pragma unroll
        for (int nt = 0; nt < 2; nt++) {
            int ncl = n0b + colbase + nt * 8 + 2 * tig;
            bool v = (ncl < ND);
            int r0 = b0 + g, r1 = r0 + 8;

            float t0 = ta[nt][0], t1 = ta[nt][1], t2 = ta[nt][2], t3 = ta[nt][3];
            if (v) {
                if (fabsf(t0) < 2e-3f) t0 = fixdot(drug_emb, r0, ncl);
                if (fabsf(t1) < 2e-3f) t1 = fixdot(drug_emb, r0, ncl + 1);
                if (fabsf(t2) < 2e-3f) t2 = fixdot(drug_emb, r1, ncl);
                if (fabsf(t3) < 2e-3f) t3 = fixdot(drug_emb, r1, ncl + 1);
            }
            float s0 = (t0 > 0.f) ? __fmaf_rn(0.5f, fast_tanh(0.5f * t0), 0.5f) : 0.f;
            float s1 = (t1 > 0.f) ? __fmaf_rn(0.5f, fast_tanh(0.5f * t1), 0.5f) : 0.f;
            float s2 = (t2 > 0.f) ? __fmaf_rn(0.5f, fast_tanh(0.5f * t2), 0.5f) : 0.f;
            float s3 = (t3 > 0.f) ? __fmaf_rn(0.5f, fast_tanh(0.5f * t3), 0.5f) : 0.f;
            if (v) {
                *(float2*)(out + (size_t)r0 * ND + ncl) = make_float2(s0, s1);
                *(float2*)(out + (size_t)r1 * ND + ncl) = make_float2(s2, s3);
            }
            cs[2 * nt]     += s0 + s2;
            cs[2 * nt + 1] += s1 + s3;

            float z0 = za[nt][0], z1 = za[nt][1], z2 = za[nt][2], z3 = za[nt][3];
            zs  += (z0 + z1) + (z2 + z3);
            as_ += (fabsf(z0) + fabsf(z1)) + (fabsf(z2) + fabsf(z3));
        }
    }

    atomicAdd(&s_cs[colbase + 2 * tig],     cs[0]);
    atomicAdd(&s_cs[colbase + 2 * tig + 1], cs[1]);
    atomicAdd(&s_cs[colbase + 8 + 2 * tig],     cs[2]);
    atomicAdd(&s_cs[colbase + 8 + 2 * tig + 1], cs[3]);

    s_red[tid] = 0.5f * zs + 0.5f * as_;
    __syncthreads();
    for (int st = 128; st; st >>= 1) {
        if (tid < st) s_red[tid] += s_red[tid + st];
        __syncthreads();
    }
    if (tid == 0) atomicAdd(&g_bce, (double)s_red[0]);

    if (tid < BN) {
        int n = n0b + tid;
        if (n < ND) g_colsum[n] = s_cs[tid];
    }
}

// ---------------- kernel 5: batch_neg gather ----------------
__global__ void k_tail2(const int* __restrict__ idx, const float* __restrict__ val) {
    __shared__ float sred[256];
    int tid = threadIdx.x;
    int i = blockIdx.x * blockDim.x + tid;
    int stride = gridDim.x * blockDim.x;
    float acc = 0.f;
    for (int j = i; j < NNZT; j += stride) acc += val[j] * g_colsum[idx[j]];
    sred[tid] = acc;
    __syncthreads();
    for (int st = 128; st; st >>= 1) {
        if (tid < st) sred[tid] += sred[tid + st];
        __syncthreads();
    }
    if (tid == 0) atomicAdd(&g_neg1, (double)sred[0]);
}

// ---------------- kernel 6: scalars ----------------
__global__ void k_final(float* __restrict__ out) {
    int b = threadIdx.x;
    __shared__ float sred[BB];
    __shared__ double scd[BB];
    float acc = 0.f;
    double cdot = 0.0;
    float sdv = g_sdiff[b] + 1e-6f;
#pragma unroll
    for (int k = 0; k < DD; k++) {
        float cm = g_common[b * DD + k];
        cdot += (double)cm * (double)g_cdacc[b * DD + k];
        float de = g_diffacc[b * DD + k] / sdv;
        float x = cm * de;
        acc += 1.0f / (1.0f + __expf(-x));
    }
    sred[b] = acc;
    scd[b] = cdot;
    __syncthreads();
    for (int st = 64; st; st >>= 1) {
        if (b < st) { sred[b] += sred[b + st]; scd[b] += scd[b + st]; }
        __syncthreads();
    }
    if (b == 0) {
        double total = g_bce - scd[0];
        out[(size_t)BB * ND]     = (float)(total / ((double)BB * (double)ND));
        out[(size_t)BB * ND + 1] = (float)(1e-6 * g_neg1 + 1e-4 * (double)sred[0]);
    }
}

// ---------------- launcher (stream overlap with event fork/join) -----------
extern "C" void kernel_launch(void* const* d_in, const int* in_sizes, int n_in,
                              void* d_out, int out_size) {
    const int*   syms     = (const int*)d_in[0];
    const float* drugs    = (const float*)d_in[1];
    const int*   simidx   = (const int*)d_in[2];
    const int*   ddi_idx  = (const int*)d_in[3];
    const float* ddi_val  = (const float*)d_in[4];
    const float* sym_emb  = (const float*)d_in[5];
    const float* drug_emb = (const float*)d_in[6];
    const float* attn_w   = (const float*)d_in[7];
    const float* attn_b   = (const float*)d_in[8];
    float* out = (float*)d_out;

    static cudaStream_t s2 = nullptr;
    static cudaEvent_t ev0 = nullptr, evN = nullptr, ev1 = nullptr;
    static bool attr_set = false;
    const int smem_mma = (2 * BB * ST + BN * ST) * 4 + BN * 4 + 256 * 4;
    if (!attr_set) {
        cudaFuncSetAttribute(k_mma, cudaFuncAttributeMaxDynamicSharedMemorySize, smem_mma);
        cudaStreamCreateWithFlags(&s2, cudaStreamNonBlocking);
        cudaEventCreateWithFlags(&ev0, cudaEventDisableTiming);
        cudaEventCreateWithFlags(&evN, cudaEventDisableTiming);
        cudaEventCreateWithFlags(&ev1, cudaEventDisableTiming);
        attr_set = true;
    }

    // main: init -> attn -> norm -> mma -> [join s2] -> tail2 -> final
    // s2:   [after init] pack -> [after norm] diffcd
    k_init<<<32, 256>>>();
    cudaEventRecord(ev0, 0);
    cudaStreamWaitEvent(s2, ev0, 0);
    k_pack<<<1024, 256, 0, s2>>>(drugs);

    k_attn<<<BB, SS>>>(syms, simidx, sym_emb, attn_w, attn_b);
    k_norm<<<(ND + 255) / 256, 256>>>(drug_emb);
    cudaEventRecord(evN, 0);
    cudaStreamWaitEvent(s2, evN, 0);
    k_diffcd<<<BB * DCB, 256, 0, s2>>>(simidx, drug_emb);
    cudaEventRecord(ev1, s2);

    k_mma<<<(ND + BN - 1) / BN, 256, smem_mma>>>(drug_emb, out);

    cudaStreamWaitEvent(0, ev1, 0);
    k_tail2<<<1024, 256>>>(ddi_idx, ddi_val);
    k_final<<<1, BB>>>(out);
}